// round 1
// baseline (speedup 1.0000x reference)
#include <cuda_runtime.h>
#include <math.h>

// Problem constants (fixed by the reference)
#define Nn 100000
#define Ee 400000
#define Rr 4
#define Gg 64
#define INF 64
#define Hh 128
#define Cc 2

// ---------------- scratch (device globals; no allocation allowed) ----------
__device__ float g_h0  [(size_t)Nn * Hh];   // relu(x @ W_in + b_in)
__device__ float g_agg [(size_t)Nn * Hh];   // per-relation aggregation buffer
__device__ float g_out1[(size_t)Nn * Hh];   // layer-1 hetero sum (pre-ReLU)
__device__ float g_out2[(size_t)Nn * Hh];   // layer-2 hetero sum
__device__ float g_rsq_out[Rr * Nn];        // deg accum -> rsqrt(max(deg,1))
__device__ float g_rsq_in [Rr * Nn];
__device__ float g_pool[Gg * Hh];
__device__ float g_cnt [Gg];

// ---------------- utility kernels ------------------------------------------
__global__ void zero_kernel(float4* __restrict__ p, int n4) {
    int i = blockIdx.x * blockDim.x + threadIdx.x;
    if (i < n4) p[i] = make_float4(0.f, 0.f, 0.f, 0.f);
}

__global__ void degree_kernel(const int* __restrict__ src, const int* __restrict__ dst) {
    int i = blockIdx.x * blockDim.x + threadIdx.x;
    if (i < Rr * Ee) {
        int r = i / Ee;
        atomicAdd(&g_rsq_out[r * Nn + src[i]], 1.f);
        atomicAdd(&g_rsq_in [r * Nn + dst[i]], 1.f);
    }
}

__global__ void rsq_kernel() {
    int i = blockIdx.x * blockDim.x + threadIdx.x;
    if (i < Rr * Nn) {
        g_rsq_out[i] = rsqrtf(fmaxf(g_rsq_out[i], 1.f));
        g_rsq_in [i] = rsqrtf(fmaxf(g_rsq_in [i], 1.f));
    }
}

// ---------------- edge scatter: agg[dst] += (relu?)(h[src]) * rsq_out[src] --
__device__ __forceinline__ void red_add_v4(float* p, float4 v) {
    asm volatile(
        "{\n\t.reg .u64 pg;\n\t"
        "cvta.to.global.u64 pg, %0;\n\t"
        "red.global.add.v4.f32 [pg], {%1,%2,%3,%4};\n\t}"
        :: "l"(p), "f"(v.x), "f"(v.y), "f"(v.z), "f"(v.w) : "memory");
}

template <int RELU_IN>
__global__ void scatter_kernel(const float* __restrict__ h,
                               const int*   __restrict__ src,
                               const int*   __restrict__ dst,
                               const float* __restrict__ rsq_out,
                               float*       __restrict__ agg) {
    int t = blockIdx.x * blockDim.x + threadIdx.x;
    int e = t >> 5;
    int lane = t & 31;
    if (e >= Ee) return;
    int s = __ldg(&src[e]);
    int d = __ldg(&dst[e]);
    float sc = __ldg(&rsq_out[s]);
    float4 v = *(const float4*)&h[(size_t)s * Hh + lane * 4];
    if (RELU_IN) {
        v.x = fmaxf(v.x, 0.f); v.y = fmaxf(v.y, 0.f);
        v.z = fmaxf(v.z, 0.f); v.w = fmaxf(v.w, 0.f);
    }
    v.x *= sc; v.y *= sc; v.z *= sc; v.w *= sc;
    red_add_v4(&agg[(size_t)d * Hh + lane * 4], v);
}

// ---------------- SGEMM: C[n,128] (+)= rowscale(A[n,K]) @ W[K,128] + b ------
// BM=64 rows, BN=128 cols (full), BK=32. 256 threads, TM=8 x TN=4 per thread.
#define BM 64
#define BN 128
#define BK 32

__global__ void gemm_kernel(const float* __restrict__ A,
                            const float* __restrict__ rowscale, // may be null
                            const float* __restrict__ W,
                            const float* __restrict__ bias,
                            float*       __restrict__ C,
                            int n, int K, int accum, int reluOut) {
    __shared__ float  As[BM][BK];       // A tile (row-scaled)
    __shared__ float4 Ws[BK][BN / 4];   // W tile as float4

    int tid  = threadIdx.x;
    int row0 = blockIdx.x * BM;
    int rg   = tid >> 5;   // 0..7  : row group (8 rows each)
    int cg   = tid & 31;   // 0..31 : col group (4 cols each)

    float acc[8][4];
#pragma unroll
    for (int i = 0; i < 8; ++i)
#pragma unroll
        for (int j = 0; j < 4; ++j) acc[i][j] = 0.f;

    for (int k0 = 0; k0 < K; k0 += BK) {
        // load A tile: 64 rows x 32 cols; 2 passes of 32 rows
#pragma unroll
        for (int p = 0; p < 2; ++p) {
            int r    = p * 32 + (tid >> 3);
            int c4   = tid & 7;
            int grow = row0 + r;
            float4 v = make_float4(0.f, 0.f, 0.f, 0.f);
            if (grow < n) {
                v = *(const float4*)&A[(size_t)grow * K + k0 + c4 * 4];
                if (rowscale) {
                    float s = rowscale[grow];
                    v.x *= s; v.y *= s; v.z *= s; v.w *= s;
                }
            }
            *(float4*)&As[r][c4 * 4] = v;
        }
        // load W tile: 32 rows x 128 cols; 4 passes of 8 rows
#pragma unroll
        for (int p = 0; p < 4; ++p) {
            int kr = p * 8 + (tid >> 5);
            int c4 = tid & 31;
            Ws[kr][c4] = *(const float4*)&W[(size_t)(k0 + kr) * BN + c4 * 4];
        }
        __syncthreads();

#pragma unroll 8
        for (int kk = 0; kk < BK; ++kk) {
            float4 w4 = Ws[kk][cg];
#pragma unroll
            for (int i = 0; i < 8; ++i) {
                float a = As[rg * 8 + i][kk];
                acc[i][0] += a * w4.x;
                acc[i][1] += a * w4.y;
                acc[i][2] += a * w4.z;
                acc[i][3] += a * w4.w;
            }
        }
        __syncthreads();
    }

    float4 bv = ((const float4*)bias)[cg];
#pragma unroll
    for (int i = 0; i < 8; ++i) {
        int grow = row0 + rg * 8 + i;
        if (grow >= n) continue;
        float4 r = make_float4(acc[i][0] + bv.x, acc[i][1] + bv.y,
                               acc[i][2] + bv.z, acc[i][3] + bv.w);
        float4* cp = (float4*)&C[(size_t)grow * BN + cg * 4];
        if (accum) {
            float4 old = *cp;
            r.x += old.x; r.y += old.y; r.z += old.z; r.w += old.w;
        }
        if (reluOut) {
            r.x = fmaxf(r.x, 0.f); r.y = fmaxf(r.y, 0.f);
            r.z = fmaxf(r.z, 0.f); r.w = fmaxf(r.w, 0.f);
        }
        *cp = r;
    }
}

// ---------------- pooling ---------------------------------------------------
__global__ void count_kernel(const int* __restrict__ gid) {
    int i = blockIdx.x * blockDim.x + threadIdx.x;
    if (i < Nn) atomicAdd(&g_cnt[gid[i]], 1.f);
}

__global__ void pool_kernel(const float* __restrict__ h, const int* __restrict__ gid) {
    int t = blockIdx.x * blockDim.x + threadIdx.x;
    int node = t >> 5;
    int lane = t & 31;
    if (node >= Nn) return;
    int g = __ldg(&gid[node]);
    float4 v = *(const float4*)&h[(size_t)node * Hh + lane * 4];
    red_add_v4(&g_pool[g * Hh + lane * 4], v);
}

// ---------------- MLP head (single block) -----------------------------------
__global__ void mlp_kernel(const float* __restrict__ Wm1, const float* __restrict__ bm1,
                           const float* __restrict__ Wm2, const float* __restrict__ bm2,
                           const float* __restrict__ Wm3, const float* __restrict__ bm3,
                           float* __restrict__ out) {
    __shared__ float z[Gg * Hh];   // 32 KB
    int tid = threadIdx.x;         // 256 threads

    for (int i = tid; i < Gg * Hh; i += 256)
        z[i] = g_pool[i] / fmaxf(g_cnt[i >> 7], 1.f);
    __syncthreads();

    float r1[32];
    // layer 1
#pragma unroll
    for (int t = 0; t < 32; ++t) {
        int o = tid + t * 256;
        int g = o >> 7, j = o & 127;
        float s = bm1[j];
        for (int k = 0; k < Hh; ++k) s += z[(g << 7) + k] * Wm1[k * Hh + j];
        r1[t] = fmaxf(s, 0.f);
    }
    __syncthreads();
#pragma unroll
    for (int t = 0; t < 32; ++t) z[tid + t * 256] = r1[t];
    __syncthreads();
    // layer 2
#pragma unroll
    for (int t = 0; t < 32; ++t) {
        int o = tid + t * 256;
        int g = o >> 7, j = o & 127;
        float s = bm2[j];
        for (int k = 0; k < Hh; ++k) s += z[(g << 7) + k] * Wm2[k * Hh + j];
        r1[t] = fmaxf(s, 0.f);
    }
    __syncthreads();
#pragma unroll
    for (int t = 0; t < 32; ++t) z[tid + t * 256] = r1[t];
    __syncthreads();
    // layer 3: [64,2]
    if (tid < Gg * Cc) {
        int g = tid >> 1, c = tid & 1;
        float s = bm3[c];
        for (int k = 0; k < Hh; ++k) s += z[(g << 7) + k] * Wm3[k * Cc + c];
        out[tid] = s;
    }
}

// ---------------- launch ----------------------------------------------------
static float* sym(const void* s) {
    void* p = nullptr;
    cudaGetSymbolAddress(&p, s);
    return (float*)p;
}

extern "C" void kernel_launch(void* const* d_in, const int* in_sizes, int n_in,
                              void* d_out, int out_size) {
    const float* x    = (const float*)d_in[0];
    const int*   src  = (const int*)  d_in[1];
    const int*   dst  = (const int*)  d_in[2];
    const int*   gid  = (const int*)  d_in[3];
    const float* W_in = (const float*)d_in[4];
    const float* b_in = (const float*)d_in[5];
    const float* W1   = (const float*)d_in[6];
    const float* b1   = (const float*)d_in[7];
    const float* W2   = (const float*)d_in[8];
    const float* b2   = (const float*)d_in[9];
    const float* Wm1  = (const float*)d_in[10];
    const float* bm1  = (const float*)d_in[11];
    const float* Wm2  = (const float*)d_in[12];
    const float* bm2  = (const float*)d_in[13];
    const float* Wm3  = (const float*)d_in[14];
    const float* bm3  = (const float*)d_in[15];
    float* out = (float*)d_out;

    float* p_h0   = sym(g_h0);
    float* p_agg  = sym(g_agg);
    float* p_out1 = sym(g_out1);
    float* p_out2 = sym(g_out2);
    float* p_rso  = sym(g_rsq_out);
    float* p_rsi  = sym(g_rsq_in);
    float* p_pool = sym(g_pool);
    float* p_cnt  = sym(g_cnt);

    const int TB = 256;
    const int NH4    = (Nn * Hh) / 4;
    const int zbNH   = (NH4 + TB - 1) / TB;
    const int RN4    = (Rr * Nn) / 4;
    const int zbRN   = (RN4 + TB - 1) / TB;
    const int gemm_blocks  = (Nn + BM - 1) / BM;
    const int scat_blocks  = (Ee * 32 + TB - 1) / TB;

    // degrees -> rsqrt
    zero_kernel<<<zbRN, TB>>>((float4*)p_rso, RN4);
    zero_kernel<<<zbRN, TB>>>((float4*)p_rsi, RN4);
    degree_kernel<<<(Rr * Ee + TB - 1) / TB, TB>>>(src, dst);
    rsq_kernel<<<(Rr * Nn + TB - 1) / TB, TB>>>();

    // h0 = relu(x @ W_in + b_in)
    gemm_kernel<<<gemm_blocks, TB>>>(x, nullptr, W_in, b_in, p_h0, Nn, INF, 0, 1);

    // layer 1: out1 = sum_r (D_in^-1/2 A_r^T D_out^-1/2 h0) @ W1_r + b1_r
    for (int r = 0; r < Rr; ++r) {
        zero_kernel<<<zbNH, TB>>>((float4*)p_agg, NH4);
        scatter_kernel<0><<<scat_blocks, TB>>>(p_h0, src + r * Ee, dst + r * Ee,
                                               p_rso + r * Nn, p_agg);
        gemm_kernel<<<gemm_blocks, TB>>>(p_agg, p_rsi + r * Nn,
                                         W1 + (size_t)r * Hh * Hh, b1 + r * Hh,
                                         p_out1, Nn, Hh, r > 0, 0);
    }

    // layer 2 (ReLU of out1 fused into the gather)
    for (int r = 0; r < Rr; ++r) {
        zero_kernel<<<zbNH, TB>>>((float4*)p_agg, NH4);
        scatter_kernel<1><<<scat_blocks, TB>>>(p_out1, src + r * Ee, dst + r * Ee,
                                               p_rso + r * Nn, p_agg);
        gemm_kernel<<<gemm_blocks, TB>>>(p_agg, p_rsi + r * Nn,
                                         W2 + (size_t)r * Hh * Hh, b2 + r * Hh,
                                         p_out2, Nn, Hh, r > 0, 0);
    }

    // per-graph mean pool
    zero_kernel<<<(Gg * Hh / 4 + TB - 1) / TB, TB>>>((float4*)p_pool, Gg * Hh / 4);
    zero_kernel<<<1, TB>>>((float4*)p_cnt, Gg / 4);
    count_kernel<<<(Nn + TB - 1) / TB, TB>>>(gid);
    pool_kernel<<<(Nn * 32 + TB - 1) / TB, TB>>>(p_out2, gid);

    // MLP head
    mlp_kernel<<<1, TB>>>(Wm1, bm1, Wm2, bm2, Wm3, bm3, out);
}